// round 1
// baseline (speedup 1.0000x reference)
#include <cuda_runtime.h>
#include <cuda_bf16.h>
#include <cstdint>

#define DIM   2048
#define HID   8192
#define BATCH 4096

// ------------------------- device scratch (no allocations allowed) ----------
__device__ __align__(256) __nv_bfloat16 g_wf [DIM*DIM];
__device__ __align__(256) __nv_bfloat16 g_wc [DIM*DIM];
__device__ __align__(256) __nv_bfloat16 g_wg [DIM*DIM];
__device__ __align__(256) __nv_bfloat16 g_wo [DIM*DIM];
__device__ __align__(256) __nv_bfloat16 g_wu [HID*DIM];
__device__ __align__(256) __nv_bfloat16 g_wg2[HID*DIM];
__device__ __align__(256) __nv_bfloat16 g_wout[DIM*HID];

__device__ __align__(256) __nv_bfloat16 g_xhi[BATCH*DIM], g_xlo[BATCH*DIM];
__device__ __align__(256) float g_F[BATCH*DIM], g_C[BATCH*DIM], g_G[BATCH*DIM];
__device__ __align__(256) __nv_bfloat16 g_thi[BATCH*DIM], g_tlo[BATCH*DIM];
__device__ __align__(256) float g_O[BATCH*DIM];
__device__ __align__(256) __nv_bfloat16 g_ohi[BATCH*DIM], g_olo[BATCH*DIM];
__device__ __align__(256) float g_GG[BATCH*HID], g_U[BATCH*HID];
__device__ __align__(256) __nv_bfloat16 g_shi[BATCH*HID], g_slo[BATCH*HID];

// ------------------------- small helpers ------------------------------------
__device__ __forceinline__ float sigmoidf_(float v) { return 1.0f / (1.0f + expf(-v)); }

__device__ __forceinline__ void cp_async16(uint32_t s, const void* g) {
    asm volatile("cp.async.cg.shared.global [%0], [%1], 16;\n" :: "r"(s), "l"(g) : "memory");
}
__device__ __forceinline__ void cp_commit() {
    asm volatile("cp.async.commit_group;\n" ::: "memory");
}
__device__ __forceinline__ void ldsm_x4(uint32_t* r, uint32_t a) {
    asm volatile("ldmatrix.sync.aligned.m8n8.x4.shared.b16 {%0,%1,%2,%3}, [%4];\n"
                 : "=r"(r[0]), "=r"(r[1]), "=r"(r[2]), "=r"(r[3]) : "r"(a));
}
__device__ __forceinline__ void mma_bf16(float* c, const uint32_t* a, const uint32_t* b) {
    asm volatile(
        "mma.sync.aligned.m16n8k16.row.col.f32.bf16.bf16.f32 "
        "{%0,%1,%2,%3}, {%4,%5,%6,%7}, {%8,%9}, {%0,%1,%2,%3};\n"
        : "+f"(c[0]), "+f"(c[1]), "+f"(c[2]), "+f"(c[3])
        : "r"(a[0]), "r"(a[1]), "r"(a[2]), "r"(a[3]), "r"(b[0]), "r"(b[1]));
}

// ------------------------- elementwise kernels ------------------------------
__global__ void tern_kernel(const float* __restrict__ w, __nv_bfloat16* __restrict__ o, int n) {
    int i = blockIdx.x * blockDim.x + threadIdx.x;
    if (i < n) {
        float v = w[i];
        float t = (fabsf(v) < 0.33f) ? 0.0f : (v > 0.0f ? 1.0f : -1.0f);
        o[i] = __float2bfloat16(t);
    }
}

__global__ void split_kernel(const float* __restrict__ v,
                             __nv_bfloat16* __restrict__ hi,
                             __nv_bfloat16* __restrict__ lo, int n) {
    int i = blockIdx.x * blockDim.x + threadIdx.x;
    if (i < n) {
        float x = v[i];
        __nv_bfloat16 h = __float2bfloat16(x);
        hi[i] = h;
        lo[i] = __float2bfloat16(x - __bfloat162float(h));
    }
}

// t = sigmoid(G) * (1 - sigmoid(F)) * silu(C)   (h_prev = 0)
__global__ void mlgru_ew_kernel(int n) {
    int i = blockIdx.x * blockDim.x + threadIdx.x;
    if (i >= n) return;
    float f  = sigmoidf_(g_F[i]);
    float c0 = g_C[i];
    float c  = c0 * sigmoidf_(c0);
    float g  = sigmoidf_(g_G[i]);
    float t  = g * (1.0f - f) * c;
    __nv_bfloat16 h = __float2bfloat16(t);
    g_thi[i] = h;
    g_tlo[i] = __float2bfloat16(t - __bfloat162float(h));
}

// s = sigmoid(GG) * silu(U)
__global__ void glu_ew_kernel(int n) {
    int i = blockIdx.x * blockDim.x + threadIdx.x;
    if (i >= n) return;
    float gg = sigmoidf_(g_GG[i]);
    float u0 = g_U[i];
    float u  = u0 * sigmoidf_(u0);
    float s  = gg * u;
    __nv_bfloat16 h = __float2bfloat16(s);
    g_shi[i] = h;
    g_slo[i] = __float2bfloat16(s - __bfloat162float(h));
}

// ------------------------- GEMM: out[M,N] = (Ahi+Alo)[M,K] @ W[N,K]^T + bias -
// 128x128 block tile, BK=32 bf16, double-buffered cp.async, mma.m16n8k16.
// K is logically doubled: first pass over Ahi, second over Alo, same W.
#define BM 128
#define BN 128
#define BK 32
#define SROW 80   // bytes per smem row (64B data + 16B pad: conflict-free ldmatrix)

__global__ __launch_bounds__(256) void gemm_bf16split(
    const __nv_bfloat16* __restrict__ Ahi,
    const __nv_bfloat16* __restrict__ Alo,
    const __nv_bfloat16* __restrict__ W,
    const float* __restrict__ bias,
    float* __restrict__ out,
    int M, int N, int K)
{
    __shared__ __align__(16) unsigned char smem[2 * 2 * BM * SROW];  // 40 KB

    const int tid  = threadIdx.x;
    const int lane = tid & 31;
    const int warp = tid >> 5;
    const int wm   = warp >> 2;   // 0..1  (64 rows each)
    const int wn   = warp & 3;    // 0..3  (32 cols each)
    const long bM  = (long)blockIdx.y * BM;
    const long bN  = (long)blockIdx.x * BN;

    const int ktH = K / BK;
    const int KT  = 2 * ktH;

    float acc[4][4][4];
    #pragma unroll
    for (int i = 0; i < 4; i++)
        #pragma unroll
        for (int j = 0; j < 4; j++)
            #pragma unroll
            for (int k = 0; k < 4; k++) acc[i][j][k] = 0.0f;

    const int lrow = tid >> 2;   // 0..63
    const int lc   = tid & 3;    // 16B chunk 0..3

    auto issue_tile = [&](int it_) {
        const __nv_bfloat16* Abase = (it_ < ktH) ? Ahi : Alo;
        long kk = (long)((it_ < ktH ? it_ : it_ - ktH) * BK);
        unsigned char* sA = smem + (it_ & 1) * (2 * BM * SROW);
        unsigned char* sB = sA + BM * SROW;
        #pragma unroll
        for (int i2 = 0; i2 < 2; i2++) {
            int r = lrow + i2 * 64;
            cp_async16((uint32_t)__cvta_generic_to_shared(sA + r * SROW + lc * 16),
                       Abase + (bM + r) * (long)K + kk + lc * 8);
            cp_async16((uint32_t)__cvta_generic_to_shared(sB + r * SROW + lc * 16),
                       W + (bN + r) * (long)K + kk + lc * 8);
        }
        cp_commit();
    };

    issue_tile(0);

    const int g1 = (lane >> 3) & 1;
    const int g2 = lane >> 4;
    const int r8 = lane & 7;

    for (int it = 0; it < KT; it++) {
        if (it + 1 < KT) {
            issue_tile(it + 1);
            asm volatile("cp.async.wait_group 1;\n" ::: "memory");
        } else {
            asm volatile("cp.async.wait_group 0;\n" ::: "memory");
        }
        __syncthreads();

        unsigned char* sA = smem + (it & 1) * (2 * BM * SROW);
        unsigned char* sB = sA + BM * SROW;

        #pragma unroll
        for (int ks = 0; ks < 2; ks++) {         // two k16 steps per BK=32
            uint32_t aF[4][4], bF[4][2];
            #pragma unroll
            for (int mi = 0; mi < 4; mi++) {
                int r = wm * 64 + mi * 16 + g1 * 8 + r8;
                int c = ks * 2 + g2;
                ldsm_x4(aF[mi], (uint32_t)__cvta_generic_to_shared(sA + r * SROW + c * 16));
            }
            #pragma unroll
            for (int nb = 0; nb < 2; nb++) {     // each x4 covers 16 n
                int r = wn * 32 + nb * 16 + g2 * 8 + r8;
                int c = ks * 2 + g1;
                uint32_t tmp[4];
                ldsm_x4(tmp, (uint32_t)__cvta_generic_to_shared(sB + r * SROW + c * 16));
                bF[nb * 2 + 0][0] = tmp[0]; bF[nb * 2 + 0][1] = tmp[1];
                bF[nb * 2 + 1][0] = tmp[2]; bF[nb * 2 + 1][1] = tmp[3];
            }
            #pragma unroll
            for (int mi = 0; mi < 4; mi++)
                #pragma unroll
                for (int nj = 0; nj < 4; nj++)
                    mma_bf16(acc[mi][nj], aF[mi], bF[nj]);
        }
        __syncthreads();
    }

    // epilogue: +bias, fp32 store
    const int cg = lane >> 2, tg = lane & 3;
    #pragma unroll
    for (int mi = 0; mi < 4; mi++) {
        #pragma unroll
        for (int nj = 0; nj < 4; nj++) {
            long row = bM + wm * 64 + mi * 16 + cg;
            long col = bN + wn * 32 + nj * 8 + tg * 2;
            float b0 = bias[col], b1 = bias[col + 1];
            float2 v0 = make_float2(acc[mi][nj][0] + b0, acc[mi][nj][1] + b1);
            float2 v1 = make_float2(acc[mi][nj][2] + b0, acc[mi][nj][3] + b1);
            *reinterpret_cast<float2*>(out + row * (long)N + col)       = v0;
            *reinterpret_cast<float2*>(out + (row + 8) * (long)N + col) = v1;
        }
    }
}

// ------------------------- host launcher ------------------------------------
extern "C" void kernel_launch(void* const* d_in, const int* in_sizes, int n_in,
                              void* d_out, int out_size)
{
    (void)in_sizes; (void)n_in; (void)out_size;
    const float* x    = (const float*)d_in[0];
    const float* wf   = (const float*)d_in[1];
    const float* bf_  = (const float*)d_in[2];
    const float* wc   = (const float*)d_in[3];
    const float* bc   = (const float*)d_in[4];
    const float* wg   = (const float*)d_in[5];
    const float* bg   = (const float*)d_in[6];
    const float* wo   = (const float*)d_in[7];
    const float* bo   = (const float*)d_in[8];
    const float* wu   = (const float*)d_in[9];
    const float* bu   = (const float*)d_in[10];
    const float* wg2  = (const float*)d_in[11];
    const float* bg2  = (const float*)d_in[12];
    const float* wout = (const float*)d_in[13];
    const float* bout = (const float*)d_in[14];
    float* out = (float*)d_out;

    void *p_wf, *p_wc, *p_wg, *p_wo, *p_wu, *p_wg2, *p_wout;
    void *p_xhi, *p_xlo, *p_F, *p_C, *p_G, *p_thi, *p_tlo;
    void *p_O, *p_ohi, *p_olo, *p_GG, *p_U, *p_shi, *p_slo;
    cudaGetSymbolAddress(&p_wf, g_wf);     cudaGetSymbolAddress(&p_wc, g_wc);
    cudaGetSymbolAddress(&p_wg, g_wg);     cudaGetSymbolAddress(&p_wo, g_wo);
    cudaGetSymbolAddress(&p_wu, g_wu);     cudaGetSymbolAddress(&p_wg2, g_wg2);
    cudaGetSymbolAddress(&p_wout, g_wout);
    cudaGetSymbolAddress(&p_xhi, g_xhi);   cudaGetSymbolAddress(&p_xlo, g_xlo);
    cudaGetSymbolAddress(&p_F, g_F);       cudaGetSymbolAddress(&p_C, g_C);
    cudaGetSymbolAddress(&p_G, g_G);
    cudaGetSymbolAddress(&p_thi, g_thi);   cudaGetSymbolAddress(&p_tlo, g_tlo);
    cudaGetSymbolAddress(&p_O, g_O);
    cudaGetSymbolAddress(&p_ohi, g_ohi);   cudaGetSymbolAddress(&p_olo, g_olo);
    cudaGetSymbolAddress(&p_GG, g_GG);     cudaGetSymbolAddress(&p_U, g_U);
    cudaGetSymbolAddress(&p_shi, g_shi);   cudaGetSymbolAddress(&p_slo, g_slo);

    const int T = 256;
    const int nDD = DIM * DIM;     // 4.2M
    const int nHD = HID * DIM;     // 16.8M
    const int nBD = BATCH * DIM;   // 8.4M
    const int nBH = BATCH * HID;   // 33.6M

    // 1) ternarize all weights (bf16, exact)
    tern_kernel<<<(nDD + T - 1) / T, T>>>(wf,   (__nv_bfloat16*)p_wf,   nDD);
    tern_kernel<<<(nDD + T - 1) / T, T>>>(wc,   (__nv_bfloat16*)p_wc,   nDD);
    tern_kernel<<<(nDD + T - 1) / T, T>>>(wg,   (__nv_bfloat16*)p_wg,   nDD);
    tern_kernel<<<(nDD + T - 1) / T, T>>>(wo,   (__nv_bfloat16*)p_wo,   nDD);
    tern_kernel<<<(nHD + T - 1) / T, T>>>(wu,   (__nv_bfloat16*)p_wu,   nHD);
    tern_kernel<<<(nHD + T - 1) / T, T>>>(wg2,  (__nv_bfloat16*)p_wg2,  nHD);
    tern_kernel<<<(nHD + T - 1) / T, T>>>(wout, (__nv_bfloat16*)p_wout, nHD);

    // 2) split x -> hi/lo bf16
    split_kernel<<<(nBD + T - 1) / T, T>>>(x, (__nv_bfloat16*)p_xhi, (__nv_bfloat16*)p_xlo, nBD);

    dim3 gridD(DIM / BN, BATCH / BM);   // (16, 32)
    dim3 gridH(HID / BN, BATCH / BM);   // (64, 32)

    // 3) F, C, G GEMMs (M=4096, N=2048, K=2048)
    gemm_bf16split<<<gridD, 256>>>((__nv_bfloat16*)p_xhi, (__nv_bfloat16*)p_xlo,
                                   (__nv_bfloat16*)p_wf, bf_, (float*)p_F, BATCH, DIM, DIM);
    gemm_bf16split<<<gridD, 256>>>((__nv_bfloat16*)p_xhi, (__nv_bfloat16*)p_xlo,
                                   (__nv_bfloat16*)p_wc, bc,  (float*)p_C, BATCH, DIM, DIM);
    gemm_bf16split<<<gridD, 256>>>((__nv_bfloat16*)p_xhi, (__nv_bfloat16*)p_xlo,
                                   (__nv_bfloat16*)p_wg, bg,  (float*)p_G, BATCH, DIM, DIM);

    // 4) t = sigmoid(G)*(1-sigmoid(F))*silu(C) -> hi/lo
    mlgru_ew_kernel<<<(nBD + T - 1) / T, T>>>(nBD);

    // 5) O = t @ Wo^T + bo
    gemm_bf16split<<<gridD, 256>>>((__nv_bfloat16*)p_thi, (__nv_bfloat16*)p_tlo,
                                   (__nv_bfloat16*)p_wo, bo, (float*)p_O, BATCH, DIM, DIM);

    // 6) split O -> hi/lo
    split_kernel<<<(nBD + T - 1) / T, T>>>((float*)p_O, (__nv_bfloat16*)p_ohi,
                                           (__nv_bfloat16*)p_olo, nBD);

    // 7) GG = o @ Wg2^T + bg2 ; U = o @ Wu^T + bu   (N=8192, K=2048)
    gemm_bf16split<<<gridH, 256>>>((__nv_bfloat16*)p_ohi, (__nv_bfloat16*)p_olo,
                                   (__nv_bfloat16*)p_wg2, bg2, (float*)p_GG, BATCH, HID, DIM);
    gemm_bf16split<<<gridH, 256>>>((__nv_bfloat16*)p_ohi, (__nv_bfloat16*)p_olo,
                                   (__nv_bfloat16*)p_wu,  bu,  (float*)p_U,  BATCH, HID, DIM);

    // 8) s = sigmoid(GG)*silu(U) -> hi/lo
    glu_ew_kernel<<<(nBH + T - 1) / T, T>>>(nBH);

    // 9) out = s @ Wout^T + bout   (N=2048, K=8192)
    gemm_bf16split<<<gridD, 256>>>((__nv_bfloat16*)p_shi, (__nv_bfloat16*)p_slo,
                                   (__nv_bfloat16*)p_wout, bout, out, BATCH, DIM, HID);
}

// round 3
// speedup vs baseline: 1.1136x; 1.1136x over previous
#include <cuda_runtime.h>
#include <cuda_bf16.h>
#include <cstdint>

#define DIM   2048
#define HID   8192
#define BATCH 4096

// ---------------- GEMM tiling ----------------
#define BM 128
#define BN 256
#define BK 32                      // bf16 K elements per stage
#define SROW 80                    // 64B data + 16B pad per row (conflict-free ldmatrix)
#define STAGES 4
#define A_STG (BM * SROW)          // 10240 B
#define B_STG (BN * SROW)          // 20480 B
#define STG   (A_STG + B_STG)      // 30720 B
#define GEMM_SMEM (STAGES * STG)   // 122880 B (dynamic)

// ---------------- device scratch ----------------
__device__ __align__(256) __nv_bfloat16 g_wf [DIM*DIM];
__device__ __align__(256) __nv_bfloat16 g_wc [DIM*DIM];
__device__ __align__(256) __nv_bfloat16 g_wg [DIM*DIM];
__device__ __align__(256) __nv_bfloat16 g_wo [DIM*DIM];
__device__ __align__(256) __nv_bfloat16 g_wu [HID*DIM];
__device__ __align__(256) __nv_bfloat16 g_wg2[HID*DIM];
__device__ __align__(256) __nv_bfloat16 g_wout[DIM*HID];

__device__ __align__(256) __nv_bfloat16 g_xhi[BATCH*DIM], g_xlo[BATCH*DIM];
__device__ __align__(256) float g_F[BATCH*DIM], g_C[BATCH*DIM], g_G[BATCH*DIM];
__device__ __align__(256) __nv_bfloat16 g_thi[BATCH*DIM], g_tlo[BATCH*DIM];
__device__ __align__(256) float g_O[BATCH*DIM];
__device__ __align__(256) __nv_bfloat16 g_ohi[BATCH*DIM], g_olo[BATCH*DIM];
__device__ __align__(256) float g_GG[BATCH*HID], g_U[BATCH*HID];
__device__ __align__(256) __nv_bfloat16 g_shi[BATCH*HID], g_slo[BATCH*HID];

// ---------------- PTX helpers ----------------
__device__ __forceinline__ uint32_t smem_u32(const void* p) {
    uint32_t a;
    asm("{ .reg .u64 t; cvta.to.shared.u64 t, %1; cvt.u32.u64 %0, t; }" : "=r"(a) : "l"(p));
    return a;
}
__device__ __forceinline__ void cp_async16(uint32_t s, const void* g) {
    asm volatile("cp.async.cg.shared.global [%0], [%1], 16;\n" :: "r"(s), "l"(g) : "memory");
}
__device__ __forceinline__ void cp_commit() {
    asm volatile("cp.async.commit_group;\n" ::: "memory");
}
__device__ __forceinline__ void ldsm_x4(uint32_t* r, uint32_t a) {
    asm volatile("ldmatrix.sync.aligned.m8n8.x4.shared.b16 {%0,%1,%2,%3}, [%4];\n"
                 : "=r"(r[0]), "=r"(r[1]), "=r"(r[2]), "=r"(r[3]) : "r"(a));
}
__device__ __forceinline__ void mma_bf16(float* c, const uint32_t* a, const uint32_t* b) {
    asm volatile(
        "mma.sync.aligned.m16n8k16.row.col.f32.bf16.bf16.f32 "
        "{%0,%1,%2,%3}, {%4,%5,%6,%7}, {%8,%9}, {%0,%1,%2,%3};\n"
        : "+f"(c[0]), "+f"(c[1]), "+f"(c[2]), "+f"(c[3])
        : "r"(a[0]), "r"(a[1]), "r"(a[2]), "r"(a[3]), "r"(b[0]), "r"(b[1]));
}

// ---------------- elementwise (vectorized) ----------------
__device__ __forceinline__ float sigmoidf_(float v) { return 1.0f / (1.0f + expf(-v)); }

__global__ void tern_kernel(const float4* __restrict__ w, uint4* __restrict__ o, int n8) {
    int i = blockIdx.x * blockDim.x + threadIdx.x;
    if (i >= n8) return;
    float4 a = w[2*i], b = w[2*i+1];
    float v[8] = {a.x, a.y, a.z, a.w, b.x, b.y, b.z, b.w};
    union { uint4 u; __nv_bfloat16 h[8]; } r;
    #pragma unroll
    for (int j = 0; j < 8; j++) {
        float t = (fabsf(v[j]) < 0.33f) ? 0.0f : (v[j] > 0.0f ? 1.0f : -1.0f);
        r.h[j] = __float2bfloat16(t);
    }
    o[i] = r.u;
}

__global__ void split_kernel(const float4* __restrict__ v,
                             uint4* __restrict__ hi, uint4* __restrict__ lo, int n8) {
    int i = blockIdx.x * blockDim.x + threadIdx.x;
    if (i >= n8) return;
    float4 a = v[2*i], b = v[2*i+1];
    float x[8] = {a.x, a.y, a.z, a.w, b.x, b.y, b.z, b.w};
    union { uint4 u; __nv_bfloat16 h[8]; } rh, rl;
    #pragma unroll
    for (int j = 0; j < 8; j++) {
        __nv_bfloat16 h = __float2bfloat16(x[j]);
        rh.h[j] = h;
        rl.h[j] = __float2bfloat16(x[j] - __bfloat162float(h));
    }
    hi[i] = rh.u; lo[i] = rl.u;
}

__global__ void mlgru_ew_kernel(int n4) {
    int i = blockIdx.x * blockDim.x + threadIdx.x;
    if (i >= n4) return;
    float4 f4 = ((const float4*)g_F)[i];
    float4 c4 = ((const float4*)g_C)[i];
    float4 g4 = ((const float4*)g_G)[i];
    float fv[4] = {f4.x, f4.y, f4.z, f4.w};
    float cv[4] = {c4.x, c4.y, c4.z, c4.w};
    float gv[4] = {g4.x, g4.y, g4.z, g4.w};
    union { uint2 u; __nv_bfloat16 h[4]; } rh, rl;
    #pragma unroll
    for (int j = 0; j < 4; j++) {
        float f = sigmoidf_(fv[j]);
        float c = cv[j] * sigmoidf_(cv[j]);
        float g = sigmoidf_(gv[j]);
        float t = g * (1.0f - f) * c;
        __nv_bfloat16 h = __float2bfloat16(t);
        rh.h[j] = h;
        rl.h[j] = __float2bfloat16(t - __bfloat162float(h));
    }
    ((uint2*)g_thi)[i] = rh.u;
    ((uint2*)g_tlo)[i] = rl.u;
}

__global__ void glu_ew_kernel(int n4) {
    int i = blockIdx.x * blockDim.x + threadIdx.x;
    if (i >= n4) return;
    float4 gg4 = ((const float4*)g_GG)[i];
    float4 u4  = ((const float4*)g_U)[i];
    float ggv[4] = {gg4.x, gg4.y, gg4.z, gg4.w};
    float uv[4]  = {u4.x, u4.y, u4.z, u4.w};
    union { uint2 u; __nv_bfloat16 h[4]; } rh, rl;
    #pragma unroll
    for (int j = 0; j < 4; j++) {
        float gg = sigmoidf_(ggv[j]);
        float u  = uv[j] * sigmoidf_(uv[j]);
        float s  = gg * u;
        __nv_bfloat16 h = __float2bfloat16(s);
        rh.h[j] = h;
        rl.h[j] = __float2bfloat16(s - __bfloat162float(h));
    }
    ((uint2*)g_shi)[i] = rh.u;
    ((uint2*)g_slo)[i] = rl.u;
}

// ---------------- HMMA GEMM --------------------------------------------------
// out[M,N] = (Ahi ++ Alo)[M,2K] @ (W ++ W)[N,2K]^T + bias    (fp32 out)
// CTA tile 128x256, warp tile 64x64 (2x4 warp grid), BK=32,
// 4-stage cp.async pipeline with a single __syncthreads per K-iteration.
__global__ __launch_bounds__(256, 1) void gemm_hmma(
    const __nv_bfloat16* __restrict__ Ahi,
    const __nv_bfloat16* __restrict__ Alo,
    const __nv_bfloat16* __restrict__ W,
    const float* __restrict__ bias,
    float* __restrict__ out,
    int M, int N, int K)
{
    extern __shared__ __align__(16) unsigned char smem[];

    const int tid  = threadIdx.x;
    const int lane = tid & 31;
    const int warp = tid >> 5;
    const int wm   = warp >> 2;   // 0..1  (64 rows)
    const int wn   = warp & 3;    // 0..3  (64 cols)
    const long bM  = (long)blockIdx.y * BM;
    const long bN  = (long)blockIdx.x * BN;

    const int ktH = K / BK;
    const int KT  = 2 * ktH;

    float acc[4][8][4];
    #pragma unroll
    for (int i = 0; i < 4; i++)
        #pragma unroll
        for (int j = 0; j < 8; j++)
            #pragma unroll
            for (int k = 0; k < 4; k++) acc[i][j][k] = 0.0f;

    auto issue_tile = [&](int it_) {
        const __nv_bfloat16* Ab = (it_ < ktH) ? Ahi : Alo;
        long kk = (long)(it_ < ktH ? it_ : it_ - ktH) * BK;
        unsigned char* s = smem + (it_ & (STAGES - 1)) * STG;
        #pragma unroll
        for (int c = tid; c < (BM + BN) * 4; c += 256) {
            int isB = (c >= BM * 4);
            int cc  = isB ? c - BM * 4 : c;
            int row = cc >> 2, kc = cc & 3;
            const __nv_bfloat16* g = isB
                ? (W  + (bN + row) * (long)K + kk + kc * 8)
                : (Ab + (bM + row) * (long)K + kk + kc * 8);
            cp_async16(smem_u32(s + (isB ? A_STG : 0) + row * SROW + kc * 16), g);
        }
        cp_commit();
    };

    issue_tile(0); issue_tile(1); issue_tile(2);

    const int g1 = (lane >> 3) & 1;
    const int g2 = lane >> 4;
    const int r8 = lane & 7;

    for (int it = 0; it < KT; it++) {
        if (it + 2 < KT)      asm volatile("cp.async.wait_group 2;\n" ::: "memory");
        else if (it + 1 < KT) asm volatile("cp.async.wait_group 1;\n" ::: "memory");
        else                  asm volatile("cp.async.wait_group 0;\n" ::: "memory");
        __syncthreads();
        if (it + 3 < KT) issue_tile(it + 3);   // overwrites stage (it-1)%4: reads done (sync)

        unsigned char* sA = smem + (it & (STAGES - 1)) * STG;
        unsigned char* sB = sA + A_STG;

        #pragma unroll
        for (int ks = 0; ks < 2; ks++) {
            uint32_t aF[4][4], bF[8][2];
            #pragma unroll
            for (int mi = 0; mi < 4; mi++) {
                int r = wm * 64 + mi * 16 + g1 * 8 + r8;
                int c = ks * 2 + g2;
                ldsm_x4(aF[mi], smem_u32(sA + r * SROW + c * 16));
            }
            #pragma unroll
            for (int nb = 0; nb < 4; nb++) {
                int r = wn * 64 + nb * 16 + g2 * 8 + r8;
                int c = ks * 2 + g1;
                uint32_t t[4];
                ldsm_x4(t, smem_u32(sB + r * SROW + c * 16));
                bF[nb * 2 + 0][0] = t[0]; bF[nb * 2 + 0][1] = t[1];
                bF[nb * 2 + 1][0] = t[2]; bF[nb * 2 + 1][1] = t[3];
            }
            #pragma unroll
            for (int mi = 0; mi < 4; mi++)
                #pragma unroll
                for (int nj = 0; nj < 8; nj++)
                    mma_bf16(acc[mi][nj], aF[mi], bF[nj]);
        }
    }

    // epilogue: +bias, fp32 store
    const int cg = lane >> 2, tg = lane & 3;
    #pragma unroll
    for (int mi = 0; mi < 4; mi++) {
        #pragma unroll
        for (int nj = 0; nj < 8; nj++) {
            long row = bM + wm * 64 + mi * 16 + cg;
            long col = bN + wn * 64 + nj * 8 + tg * 2;
            float b0 = bias[col], b1 = bias[col + 1];
            float2 v0 = make_float2(acc[mi][nj][0] + b0, acc[mi][nj][1] + b1);
            float2 v1 = make_float2(acc[mi][nj][2] + b0, acc[mi][nj][3] + b1);
            *reinterpret_cast<float2*>(out + row * (long)N + col)       = v0;
            *reinterpret_cast<float2*>(out + (row + 8) * (long)N + col) = v1;
        }
    }
}

// ---------------- host launcher ----------------
extern "C" void kernel_launch(void* const* d_in, const int* in_sizes, int n_in,
                              void* d_out, int out_size)
{
    (void)in_sizes; (void)n_in; (void)out_size;
    const float* x    = (const float*)d_in[0];
    const float* wf   = (const float*)d_in[1];
    const float* bf_  = (const float*)d_in[2];
    const float* wc   = (const float*)d_in[3];
    const float* bc   = (const float*)d_in[4];
    const float* wg   = (const float*)d_in[5];
    const float* bg   = (const float*)d_in[6];
    const float* wo   = (const float*)d_in[7];
    const float* bo   = (const float*)d_in[8];
    const float* wu   = (const float*)d_in[9];
    const float* bu   = (const float*)d_in[10];
    const float* wg2  = (const float*)d_in[11];
    const float* bg2  = (const float*)d_in[12];
    const float* wout = (const float*)d_in[13];
    const float* bout = (const float*)d_in[14];
    float* out = (float*)d_out;

    cudaFuncSetAttribute(gemm_hmma, cudaFuncAttributeMaxDynamicSharedMemorySize, GEMM_SMEM);

    void *p_wf, *p_wc, *p_wg, *p_wo, *p_wu, *p_wg2, *p_wout;
    void *p_xhi, *p_xlo, *p_F, *p_C, *p_G, *p_thi, *p_tlo;
    void *p_O, *p_ohi, *p_olo, *p_GG, *p_U, *p_shi, *p_slo;
    cudaGetSymbolAddress(&p_wf, g_wf);     cudaGetSymbolAddress(&p_wc, g_wc);
    cudaGetSymbolAddress(&p_wg, g_wg);     cudaGetSymbolAddress(&p_wo, g_wo);
    cudaGetSymbolAddress(&p_wu, g_wu);     cudaGetSymbolAddress(&p_wg2, g_wg2);
    cudaGetSymbolAddress(&p_wout, g_wout);
    cudaGetSymbolAddress(&p_xhi, g_xhi);   cudaGetSymbolAddress(&p_xlo, g_xlo);
    cudaGetSymbolAddress(&p_F, g_F);       cudaGetSymbolAddress(&p_C, g_C);
    cudaGetSymbolAddress(&p_G, g_G);
    cudaGetSymbolAddress(&p_thi, g_thi);   cudaGetSymbolAddress(&p_tlo, g_tlo);
    cudaGetSymbolAddress(&p_O, g_O);
    cudaGetSymbolAddress(&p_ohi, g_ohi);   cudaGetSymbolAddress(&p_olo, g_olo);
    cudaGetSymbolAddress(&p_GG, g_GG);     cudaGetSymbolAddress(&p_U, g_U);
    cudaGetSymbolAddress(&p_shi, g_shi);   cudaGetSymbolAddress(&p_slo, g_slo);

    const int T = 256;
    const int nDD = DIM * DIM, nHD = HID * DIM, nBD = BATCH * DIM, nBH = BATCH * HID;

    dim3 gridD(DIM / BN, BATCH / BM);   // (8, 32)
    dim3 gridH(HID / BN, BATCH / BM);   // (32, 32)

    // 5 launches first so ncu (-s 5 -c 1) profiles the first GEMM
    tern_kernel<<<(nDD/8 + T - 1)/T, T>>>((const float4*)wf, (uint4*)p_wf, nDD/8);
    tern_kernel<<<(nDD/8 + T - 1)/T, T>>>((const float4*)wc, (uint4*)p_wc, nDD/8);
    tern_kernel<<<(nDD/8 + T - 1)/T, T>>>((const float4*)wg, (uint4*)p_wg, nDD/8);
    tern_kernel<<<(nDD/8 + T - 1)/T, T>>>((const float4*)wo, (uint4*)p_wo, nDD/8);
    split_kernel<<<(nBD/8 + T - 1)/T, T>>>((const float4*)x, (uint4*)p_xhi, (uint4*)p_xlo, nBD/8);

    gemm_hmma<<<gridD, 256, GEMM_SMEM>>>((__nv_bfloat16*)p_xhi, (__nv_bfloat16*)p_xlo,
                                         (__nv_bfloat16*)p_wf, bf_, (float*)p_F, BATCH, DIM, DIM);
    gemm_hmma<<<gridD, 256, GEMM_SMEM>>>((__nv_bfloat16*)p_xhi, (__nv_bfloat16*)p_xlo,
                                         (__nv_bfloat16*)p_wc, bc,  (float*)p_C, BATCH, DIM, DIM);
    gemm_hmma<<<gridD, 256, GEMM_SMEM>>>((__nv_bfloat16*)p_xhi, (__nv_bfloat16*)p_xlo,
                                         (__nv_bfloat16*)p_wg, bg,  (float*)p_G, BATCH, DIM, DIM);

    mlgru_ew_kernel<<<(nBD/4 + T - 1)/T, T>>>(nBD/4);

    gemm_hmma<<<gridD, 256, GEMM_SMEM>>>((__nv_bfloat16*)p_thi, (__nv_bfloat16*)p_tlo,
                                         (__nv_bfloat16*)p_wo, bo, (float*)p_O, BATCH, DIM, DIM);

    split_kernel<<<(nBD/8 + T - 1)/T, T>>>((const float4*)p_O, (uint4*)p_ohi, (uint4*)p_olo, nBD/8);

    tern_kernel<<<(nHD/8 + T - 1)/T, T>>>((const float4*)wg2,  (uint4*)p_wg2,  nHD/8);
    tern_kernel<<<(nHD/8 + T - 1)/T, T>>>((const float4*)wu,   (uint4*)p_wu,   nHD/8);
    tern_kernel<<<(nHD/8 + T - 1)/T, T>>>((const float4*)wout, (uint4*)p_wout, nHD/8);

    gemm_hmma<<<gridH, 256, GEMM_SMEM>>>((__nv_bfloat16*)p_ohi, (__nv_bfloat16*)p_olo,
                                         (__nv_bfloat16*)p_wg2, bg2, (float*)p_GG, BATCH, HID, DIM);
    gemm_hmma<<<gridH, 256, GEMM_SMEM>>>((__nv_bfloat16*)p_ohi, (__nv_bfloat16*)p_olo,
                                         (__nv_bfloat16*)p_wu,  bu,  (float*)p_U,  BATCH, HID, DIM);

    glu_ew_kernel<<<(nBH/4 + T - 1)/T, T>>>(nBH/4);

    gemm_hmma<<<gridD, 256, GEMM_SMEM>>>((__nv_bfloat16*)p_shi, (__nv_bfloat16*)p_slo,
                                         (__nv_bfloat16*)p_wout, bout, out, BATCH, DIM, HID);
}